// round 10
// baseline (speedup 1.0000x reference)
#include <cuda_runtime.h>
#include <math.h>
#include <stdint.h>

// Problem constants
#define BSZ    2048
#define LATENT 128
#define NCLS   8
#define HID    1024
#define DFEAT  512
#define NMAX   4096
#define PADMAX 3072   // per-class segments 128-aligned

__constant__ int d_counts[8] = {1024,1536,2048,2560,3072,3584,3840,4096};

// Scratch (static device globals, zero-initialized)
__device__ float g_h[BSZ * HID];            // tf32-exact values
__device__ float g_Tc[PADMAX * HID];        // tf32-exact; pad rows stay 0
__device__ float g_logits[PADMAX * NMAX];   // exp(logit), tf32-exact
__device__ float g_partial[PADMAX * 32];    // per-(row, n-tile) exp sums
__device__ int   g_perm[PADMAX];
__device__ int   g_pos[BSZ];
__device__ int   g_off[9];
__device__ int   g_end[8];

__device__ __forceinline__ float gelu_exact(float v) {
    return 0.5f * v * (1.0f + erff(v * 0.70710678118654752f));
}
__device__ __forceinline__ uint32_t f2tf(float x) {
    uint32_t r; asm("cvt.rna.tf32.f32 %0, %1;" : "=r"(r) : "f"(x)); return r;
}
__device__ __forceinline__ float tf32r(float x) {   // round fp32 -> nearest tf32 value
    return __uint_as_float(f2tf(x));
}
__device__ __forceinline__ void mma8(float* c, uint32_t a0, uint32_t a1,
                                     uint32_t a2, uint32_t a3,
                                     uint32_t b0, uint32_t b1) {
    asm volatile(
        "mma.sync.aligned.m16n8k8.row.col.f32.tf32.tf32.f32 "
        "{%0,%1,%2,%3}, {%4,%5,%6,%7}, {%8,%9}, {%0,%1,%2,%3};"
        : "+f"(c[0]), "+f"(c[1]), "+f"(c[2]), "+f"(c[3])
        : "r"(a0), "r"(a1), "r"(a2), "r"(a3), "r"(b0), "r"(b1));
}
// ldmatrix.x4 on tf32-as-2xb16: lane i of tile gets row i>>2, tf32-col i&3 —
// exactly the m16n8k8 tf32 A-fragment layout. Lane groups supply rows of the
// four 8x4 tiles: g0=(m,k) g1=(m+8,k) g2=(m,k+4) g3=(m+8,k+4).
__device__ __forceinline__ void ldsm4(uint32_t& a0, uint32_t& a1,
                                      uint32_t& a2, uint32_t& a3, uint32_t addr) {
    asm volatile("ldmatrix.sync.aligned.m8n8.x4.shared.b16 {%0,%1,%2,%3}, [%4];"
                 : "=r"(a0), "=r"(a1), "=r"(a2), "=r"(a3) : "r"(addr));
}
__device__ __forceinline__ void cp16(uint32_t dst, const float* src) {
    asm volatile("cp.async.cg.shared.global [%0], [%1], 16;" :: "r"(dst), "l"(src));
}
#define CP_COMMIT() asm volatile("cp.async.commit_group;" ::: "memory")
#define CP_WAIT1()  asm volatile("cp.async.wait_group 1;" ::: "memory")
#define CP_WAIT0()  asm volatile("cp.async.wait_group 0;" ::: "memory")

// ===========================================================================
// GEMM core: 128x128 CTA tile, K-chunk 32, 3-stage cp.async pipeline
// (ONE __syncthreads per chunk), 256 threads = 8 warps (2x4), warp tile
// 64x32, mma.m16n8k8 tf32. A fragments via ldmatrix.x4 (1 instr per mt,ks);
// B fragments scalar LDS + rna cvt (inputs can't be pre-rounded).
//   CVTA=1: A not tf32-exact (raw input z) -> cvt ldmatrix outputs.
// Dynamic SMEM (floats):
//   As[st][128][36]  at  st*4608            (st in 0..2)
//   Bs[st][32][136]  at  13824 + st*4352
// Total 26880 floats = 107520 B.
// ===========================================================================
#define ASF  4608
#define BOFF 13824
#define BSF  4352
#define SMEM_BYTES 107520

#define GEMM_ISSUE(kb, st)                                                    \
    {                                                                         \
        const float* asrc = Abase + (size_t)ar * LDAv + (kb) * 32 + ac;       \
        uint32_t adst = smbase + (uint32_t)(((st) * ASF + ar * 36 + ac) * 4); \
        _Pragma("unroll")                                                     \
        for (int i = 0; i < 4; i++)                                           \
            cp16(adst + i * (32 * 36 * 4), asrc + (size_t)(i * 32) * LDAv);   \
        const float* bsrc = Bbase + (size_t)((kb) * 32 + ar) * LDBv + ac;     \
        uint32_t bdst = smbase + (uint32_t)((BOFF + (st) * BSF + ar * 136 + ac) * 4); \
        _Pragma("unroll")                                                     \
        for (int i = 0; i < 4; i++)                                           \
            cp16(bdst + i * (32 * 4), bsrc + i * 32);                         \
    }

#define GEMM_COMPUTE(st, CVTA)                                                \
    {                                                                         \
    const uint32_t abase = smbase + (uint32_t)(st) * 18432u + a_lane_off;     \
    _Pragma("unroll")                                                         \
    for (int ks = 0; ks < 4; ks++) {                                          \
        const float* Bp0 = smem + BOFF + (st) * BSF + (ks * 8 + l4) * 136;    \
        const float* Bp1 = Bp0 + 4 * 136;                                     \
        uint32_t bf0[4], bf1[4];                                              \
        _Pragma("unroll")                                                     \
        for (int nt = 0; nt < 4; nt++) {                                      \
            int n = wn + nt * 8 + l28;                                        \
            bf0[nt] = f2tf(Bp0[n]);                                           \
            bf1[nt] = f2tf(Bp1[n]);                                           \
        }                                                                     \
        _Pragma("unroll")                                                     \
        for (int mt = 0; mt < 4; mt++) {                                      \
            uint32_t a0, a1, a2, a3;                                          \
            ldsm4(a0, a1, a2, a3, abase + mt * 2304u + ks * 32u);             \
            if (CVTA) {                                                       \
                a0 = f2tf(__uint_as_float(a0));                               \
                a1 = f2tf(__uint_as_float(a1));                               \
                a2 = f2tf(__uint_as_float(a2));                               \
                a3 = f2tf(__uint_as_float(a3));                               \
            }                                                                 \
            _Pragma("unroll")                                                 \
            for (int nt = 0; nt < 4; nt++)                                    \
                mma8(c[mt][nt], a0, a1, a2, a3, bf0[nt], bf1[nt]);            \
        }                                                                     \
    } }

// Pipeline order per iteration kb: wait(kb landed) -> sync -> issue(kb+2)
// -> compute(kb). The sync certifies all warps finished compute(kb-1), so
// overwriting slot (kb+2)%3 == (kb-1)%3 is safe.
#define GEMM_BODY(APTR, LDA, BPTR, LDB, NK, CVTA)                             \
    extern __shared__ float smem[];                                           \
    const uint32_t smbase = (uint32_t)__cvta_generic_to_shared(smem);         \
    const int tid  = threadIdx.x;                                             \
    const int lane = tid & 31, wrp = tid >> 5;                                \
    const int l4 = lane & 3, l28 = lane >> 2;                                 \
    const int wm = (wrp >> 2) * 64, wn = (wrp & 3) * 32;                      \
    const int lg = lane >> 3, lrow = lane & 7;                                \
    const uint32_t a_lane_off =                                               \
        (uint32_t)(((wm + (lg & 1) * 8 + lrow) * 36 + (lg >> 1) * 4) * 4);    \
    float c[4][4][4];                                                         \
    _Pragma("unroll") for (int i = 0; i < 4; i++)                             \
    _Pragma("unroll") for (int j = 0; j < 4; j++)                             \
    _Pragma("unroll") for (int q = 0; q < 4; q++) c[i][j][q] = 0.f;           \
    const int ar = tid >> 3, ac = (tid & 7) * 4;                              \
    const float* Abase = (APTR);                                              \
    const float* Bbase = (BPTR);                                              \
    const int LDAv = (int)(LDA), LDBv = (int)(LDB);                           \
    const int nk = (NK);                                                      \
    int st = 0;                                                               \
    GEMM_ISSUE(0, 0); CP_COMMIT();                                            \
    if (nk > 1) { GEMM_ISSUE(1, 1); }                                         \
    CP_COMMIT();                                                              \
    for (int kb = 0; kb < nk; kb++) {                                         \
        if (kb + 1 < nk) { CP_WAIT1(); } else { CP_WAIT0(); }                 \
        __syncthreads();                                                      \
        if (kb + 2 < nk) {                                                    \
            int s2 = st + 2 - ((st >= 1) ? 3 : 0);                            \
            GEMM_ISSUE(kb + 2, s2); CP_COMMIT();                              \
        }                                                                     \
        GEMM_COMPUTE(st, CVTA);                                               \
        st = (st == 2) ? 0 : st + 1;                                          \
    }

// Epilogue fragment mapping: rows r0 = m0+wm+mt*16+l28, r1 = r0+8;
// cols n = n0+wn+nt*8+2*l4 (pair n, n+1): c[mt][nt][0..1] row r0, [2..3] row r1.

// ---------------------------------------------------------------------------
__global__ void group_kernel(const int* __restrict__ cid) {
    __shared__ int s_cnt[8], s_off[8], s_cur[8];
    int t = threadIdx.x;
    if (t < 8) { s_cnt[t] = 0; s_cur[t] = 0; }
    __syncthreads();
    for (int m = t; m < BSZ; m += blockDim.x) atomicAdd(&s_cnt[cid[m]], 1);
    __syncthreads();
    if (t == 0) {
        int o = 0;
        for (int cc = 0; cc < 8; cc++) {
            s_off[cc] = o; g_off[cc] = o; g_end[cc] = o + s_cnt[cc];
            o = (o + s_cnt[cc] + 127) & ~127;
        }
        g_off[8] = o;
    }
    __syncthreads();
    for (int m = t; m < BSZ; m += blockDim.x) {
        int cc = cid[m];
        int p = s_off[cc] + atomicAdd(&s_cur[cc], 1);
        g_perm[p] = m; g_pos[m] = p;
    }
}

// ---------------------------------------------------------------------------
__global__ __launch_bounds__(256, 2)
void mlp1_kernel(const float* __restrict__ z, const int* __restrict__ cid,
                 const float* __restrict__ W1, const float* __restrict__ b1) {
    const int m0 = blockIdx.y * 128, n0 = blockIdx.x * 128;
    GEMM_BODY(z + (size_t)m0 * LATENT, LATENT, W1 + n0, HID, LATENT / 32, 1);

    #pragma unroll
    for (int mt = 0; mt < 4; mt++) {
        int r0 = m0 + wm + mt * 16 + l28;
        int r1 = r0 + 8;
        const float* w0 = W1 + (size_t)(LATENT + cid[r0]) * HID;
        const float* w1 = W1 + (size_t)(LATENT + cid[r1]) * HID;
        #pragma unroll
        for (int nt = 0; nt < 4; nt++) {
            int n = n0 + wn + nt * 8 + 2 * l4;
            float2 bb = *(const float2*)&b1[n];
            float2 wa = *(const float2*)&w0[n];
            float2 wb = *(const float2*)&w1[n];
            float2 o0 = make_float2(tf32r(gelu_exact(c[mt][nt][0] + bb.x + wa.x)),
                                    tf32r(gelu_exact(c[mt][nt][1] + bb.y + wa.y)));
            float2 o1 = make_float2(tf32r(gelu_exact(c[mt][nt][2] + bb.x + wb.x)),
                                    tf32r(gelu_exact(c[mt][nt][3] + bb.y + wb.y)));
            *(float2*)&g_h[(size_t)r0 * HID + n] = o0;
            *(float2*)&g_h[(size_t)r1 * HID + n] = o1;
        }
    }
}

// ---------------------------------------------------------------------------
__global__ __launch_bounds__(256, 2)
void mlp2_kernel(const float* __restrict__ W2, const float* __restrict__ b2) {
    const int m0 = blockIdx.y * 128, n0 = blockIdx.x * 128;
    GEMM_BODY(g_h + (size_t)m0 * HID, HID, W2 + n0, HID, HID / 32, 0);

    #pragma unroll
    for (int mt = 0; mt < 4; mt++) {
        int r0 = m0 + wm + mt * 16 + l28;
        int r1 = r0 + 8;
        int p0 = g_pos[r0], p1 = g_pos[r1];
        #pragma unroll
        for (int nt = 0; nt < 4; nt++) {
            int n = n0 + wn + nt * 8 + 2 * l4;
            float2 bb = *(const float2*)&b2[n];
            float2 o0 = make_float2(tf32r(gelu_exact(c[mt][nt][0] + bb.x)),
                                    tf32r(gelu_exact(c[mt][nt][1] + bb.y)));
            float2 o1 = make_float2(tf32r(gelu_exact(c[mt][nt][2] + bb.x)),
                                    tf32r(gelu_exact(c[mt][nt][3] + bb.y)));
            *(float2*)&g_Tc[(size_t)p0 * HID + n] = o0;
            *(float2*)&g_Tc[(size_t)p1 * HID + n] = o1;
        }
    }
}

// ---------------------------------------------------------------------------
// logits: writes tf32-rounded exp(t@Wa + ba) and per-(row, n-tile) partials.
// No max-subtraction: logits are O(0.05) by construction.
// ---------------------------------------------------------------------------
__global__ __launch_bounds__(256, 2)
void logits_kernel(const float* __restrict__ Wa, const float* __restrict__ ba) {
    const int pt0 = blockIdx.y * 128;
    if (pt0 >= g_off[8]) return;
    int cls = 0;
    #pragma unroll
    for (int i = 0; i < 8; i++) if (g_off[i + 1] <= pt0) cls = i + 1;
    const int Nc = d_counts[cls];
    const int n0 = blockIdx.x * 128;
    if (n0 >= Nc) return;
    const int m0 = pt0;

    __shared__ float rowpart[4][128];

    GEMM_BODY(g_Tc + (size_t)m0 * HID, HID,
              Wa + (size_t)cls * HID * NMAX + n0, NMAX, HID / 32, 0);

    const float* brow = ba + (size_t)cls * NMAX;
    #pragma unroll
    for (int mt = 0; mt < 4; mt++) {
        int lr0 = wm + mt * 16 + l28;
        int r0 = m0 + lr0;
        int r1 = r0 + 8;
        float s0 = 0.f, s1 = 0.f;
        #pragma unroll
        for (int nt = 0; nt < 4; nt++) {
            int n = n0 + wn + nt * 8 + 2 * l4;
            float2 bb = *(const float2*)&brow[n];
            float2 e0 = make_float2(tf32r(__expf(c[mt][nt][0] + bb.x)),
                                    tf32r(__expf(c[mt][nt][1] + bb.y)));
            float2 e1 = make_float2(tf32r(__expf(c[mt][nt][2] + bb.x)),
                                    tf32r(__expf(c[mt][nt][3] + bb.y)));
            s0 += e0.x + e0.y; s1 += e1.x + e1.y;
            *(float2*)&g_logits[(size_t)r0 * NMAX + n] = e0;
            *(float2*)&g_logits[(size_t)r1 * NMAX + n] = e1;
        }
        s0 += __shfl_xor_sync(0xffffffffu, s0, 1);
        s0 += __shfl_xor_sync(0xffffffffu, s0, 2);
        s1 += __shfl_xor_sync(0xffffffffu, s1, 1);
        s1 += __shfl_xor_sync(0xffffffffu, s1, 2);
        if (l4 == 0) {
            rowpart[wrp & 3][lr0] = s0;
            rowpart[wrp & 3][lr0 + 8] = s1;
        }
    }
    __syncthreads();
    if (tid < 128) {
        float s = rowpart[0][tid] + rowpart[1][tid] + rowpart[2][tid] + rowpart[3][tid];
        g_partial[(size_t)(m0 + tid) * 32 + blockIdx.x] = s;
    }
}

// ---------------------------------------------------------------------------
// out: computes 1/sum from g_partial at entry (inv_kernel folded in), then
// GEMM against Xbuf with normalization + scatter in the epilogue.
// ---------------------------------------------------------------------------
__global__ __launch_bounds__(256, 2)
void out_kernel(const float* __restrict__ Xbuf, float* __restrict__ out) {
    const int pt0 = blockIdx.y * 128;
    if (pt0 >= g_off[8]) return;
    int cls = 0;
    #pragma unroll
    for (int i = 0; i < 8; i++) if (g_off[i + 1] <= pt0) cls = i + 1;
    const int Nc = d_counts[cls];
    const int endc = g_end[cls];
    const int n0 = blockIdx.x * 128;
    const int m0 = pt0;

    __shared__ float s_inv[128];
    {
        int t = threadIdx.x;
        if (t < 128) {
            int ntile = Nc >> 7;
            float s = 0.f;
            for (int i = 0; i < ntile; i++)
                s += g_partial[(size_t)(pt0 + t) * 32 + i];
            s_inv[t] = 1.0f / s;    // pad rows: finite garbage, masked below
        }
    }

    GEMM_BODY(g_logits + (size_t)m0 * NMAX, NMAX,
              Xbuf + (size_t)cls * NMAX * DFEAT + n0, DFEAT, Nc / 32, 0);

    #pragma unroll
    for (int mt = 0; mt < 4; mt++) {
        int r0 = m0 + wm + mt * 16 + l28;
        int r1 = r0 + 8;
        bool v0 = r0 < endc, v1 = r1 < endc;
        int dm0 = v0 ? g_perm[r0] : 0;
        int dm1 = v1 ? g_perm[r1] : 0;
        float i0 = s_inv[r0 - m0];
        float i1 = s_inv[r1 - m0];
        #pragma unroll
        for (int nt = 0; nt < 4; nt++) {
            int n = n0 + wn + nt * 8 + 2 * l4;
            if (v0) {
                float2 o0 = make_float2(c[mt][nt][0] * i0, c[mt][nt][1] * i0);
                *(float2*)&out[(size_t)dm0 * DFEAT + n] = o0;
            }
            if (v1) {
                float2 o1 = make_float2(c[mt][nt][2] * i1, c[mt][nt][3] * i1);
                *(float2*)&out[(size_t)dm1 * DFEAT + n] = o1;
            }
        }
    }
}

// ---------------------------------------------------------------------------
extern "C" void kernel_launch(void* const* d_in, const int* in_sizes, int n_in,
                              void* d_out, int out_size) {
    const float* z   = (const float*)d_in[0];
    const int*   cid = (const int*)  d_in[1];
    const float* W1  = (const float*)d_in[2];
    const float* b1  = (const float*)d_in[3];
    const float* W2  = (const float*)d_in[4];
    const float* b2  = (const float*)d_in[5];
    const float* Wa  = (const float*)d_in[6];
    const float* ba  = (const float*)d_in[7];
    const float* Xb  = (const float*)d_in[8];
    float* out = (float*)d_out;

    static int attr_done = 0;
    if (!attr_done) {
        cudaFuncSetAttribute(mlp1_kernel,   cudaFuncAttributeMaxDynamicSharedMemorySize, SMEM_BYTES);
        cudaFuncSetAttribute(mlp2_kernel,   cudaFuncAttributeMaxDynamicSharedMemorySize, SMEM_BYTES);
        cudaFuncSetAttribute(logits_kernel, cudaFuncAttributeMaxDynamicSharedMemorySize, SMEM_BYTES);
        cudaFuncSetAttribute(out_kernel,    cudaFuncAttributeMaxDynamicSharedMemorySize, SMEM_BYTES);
        attr_done = 1;
    }

    group_kernel<<<1, 1024>>>(cid);
    mlp1_kernel<<<dim3(HID / 128, BSZ / 128), 256, SMEM_BYTES>>>(z, cid, W1, b1);
    mlp2_kernel<<<dim3(HID / 128, BSZ / 128), 256, SMEM_BYTES>>>(W2, b2);
    logits_kernel<<<dim3(NMAX / 128, PADMAX / 128), 256, SMEM_BYTES>>>(Wa, ba);
    out_kernel<<<dim3(DFEAT / 128, PADMAX / 128), 256, SMEM_BYTES>>>(Xb, out);
}

// round 13
// speedup vs baseline: 1.1049x; 1.1049x over previous
#include <cuda_runtime.h>
#include <math.h>
#include <stdint.h>

// Problem constants
#define BSZ    2048
#define LATENT 128
#define NCLS   8
#define HID    1024
#define DFEAT  512
#define NMAX   4096
#define PADMAX 2560   // per-class segments 64-aligned

__constant__ int d_counts[8] = {1024,1536,2048,2560,3072,3584,3840,4096};

// Scratch (static device globals, zero-initialized)
__device__ float g_h[BSZ * HID];            // tf32-exact values
__device__ float g_Tc[PADMAX * HID];        // tf32-exact; pad rows stay 0
__device__ float g_logits[PADMAX * NMAX];   // exp(logit), tf32-exact
__device__ float g_partial[PADMAX * 32];    // per-(row, n-tile) exp sums
__device__ int   g_perm[PADMAX];
__device__ int   g_pos[BSZ];
__device__ int   g_off[9];
__device__ int   g_end[8];

__device__ __forceinline__ float gelu_exact(float v) {
    return 0.5f * v * (1.0f + erff(v * 0.70710678118654752f));
}
__device__ __forceinline__ uint32_t f2tf(float x) {
    uint32_t r; asm("cvt.rna.tf32.f32 %0, %1;" : "=r"(r) : "f"(x)); return r;
}
__device__ __forceinline__ float tf32r(float x) {
    return __uint_as_float(f2tf(x));
}
__device__ __forceinline__ void mma8(float* c, uint32_t a0, uint32_t a1,
                                     uint32_t a2, uint32_t a3,
                                     uint32_t b0, uint32_t b1) {
    asm volatile(
        "mma.sync.aligned.m16n8k8.row.col.f32.tf32.tf32.f32 "
        "{%0,%1,%2,%3}, {%4,%5,%6,%7}, {%8,%9}, {%0,%1,%2,%3};"
        : "+f"(c[0]), "+f"(c[1]), "+f"(c[2]), "+f"(c[3])
        : "r"(a0), "r"(a1), "r"(a2), "r"(a3), "r"(b0), "r"(b1));
}
// ldmatrix.x4 on tf32-as-2xb16: gives exactly the m16n8k8 tf32 A fragment.
__device__ __forceinline__ void ldsm4(uint32_t& a0, uint32_t& a1,
                                      uint32_t& a2, uint32_t& a3, uint32_t addr) {
    asm volatile("ldmatrix.sync.aligned.m8n8.x4.shared.b16 {%0,%1,%2,%3}, [%4];"
                 : "=r"(a0), "=r"(a1), "=r"(a2), "=r"(a3) : "r"(addr));
}
__device__ __forceinline__ void cp16(uint32_t dst, const float* src) {
    asm volatile("cp.async.cg.shared.global [%0], [%1], 16;" :: "r"(dst), "l"(src));
}
#define CP_COMMIT() asm volatile("cp.async.commit_group;" ::: "memory")
#define CP_WAIT1()  asm volatile("cp.async.wait_group 1;" ::: "memory")
#define CP_WAIT0()  asm volatile("cp.async.wait_group 0;" ::: "memory")

// ===========================================================================
// GEMM core, parameterized M-tile (MT*16 rows per warp-row group, 2 warp rows):
//   MT=4, AI=4: 128xN tile (mlp kernels)   MT=2, AI=2: 64xN tile (grouped)
// K-chunk 32, 3-stage cp.async pipeline, ONE __syncthreads per chunk,
// 256 threads = 8 warps (2 x 4), mma.m16n8k8 tf32.
// SMEM (floats): As[st][M][36] at st*ASTRIDE; Bs[st][32][136] at BOFFv+st*4352.
// ===========================================================================
#define BSF  4352
#define SMEM_BYTES_128 ((4608 * 3 + BSF * 3) * 4)    // 107520
#define SMEM_BYTES_64  ((2304 * 3 + BSF * 3) * 4)    //  79872

#define GEMM_ISSUE(kb, st, AI, ASTRIDE, BOFFv)                                \
    {                                                                         \
        const float* asrc = Abase + (size_t)ar * LDAv + (kb) * 32 + ac;       \
        uint32_t adst = smbase + (uint32_t)(((st) * (ASTRIDE) + ar * 36 + ac) * 4); \
        _Pragma("unroll")                                                     \
        for (int i = 0; i < (AI); i++)                                        \
            cp16(adst + i * (32 * 36 * 4), asrc + (size_t)(i * 32) * LDAv);   \
        const float* bsrc = Bbase + (size_t)((kb) * 32 + ar) * LDBv + ac;     \
        uint32_t bdst = smbase + (uint32_t)(((BOFFv) + (st) * BSF + ar * 136 + ac) * 4); \
        _Pragma("unroll")                                                     \
        for (int i = 0; i < 4; i++)                                           \
            cp16(bdst + i * (32 * 4), bsrc + i * 32);                         \
    }

#define GEMM_COMPUTE(st, CVTA, MT, ASTRIDE, BOFFv)                            \
    {                                                                         \
    const uint32_t abase = smbase + (uint32_t)(st) * ((ASTRIDE) * 4u) + a_lane_off; \
    _Pragma("unroll")                                                         \
    for (int ks = 0; ks < 4; ks++) {                                          \
        const float* Bp0 = smem + (BOFFv) + (st) * BSF + (ks * 8 + l4) * 136; \
        const float* Bp1 = Bp0 + 4 * 136;                                     \
        uint32_t bf0[4], bf1[4];                                              \
        _Pragma("unroll")                                                     \
        for (int nt = 0; nt < 4; nt++) {                                      \
            int n = wn + nt * 8 + l28;                                        \
            bf0[nt] = f2tf(Bp0[n]);                                           \
            bf1[nt] = f2tf(Bp1[n]);                                           \
        }                                                                     \
        _Pragma("unroll")                                                     \
        for (int mt = 0; mt < (MT); mt++) {                                   \
            uint32_t a0, a1, a2, a3;                                          \
            ldsm4(a0, a1, a2, a3, abase + mt * 2304u + ks * 32u);             \
            if (CVTA) {                                                       \
                a0 = f2tf(__uint_as_float(a0));                               \
                a1 = f2tf(__uint_as_float(a1));                               \
                a2 = f2tf(__uint_as_float(a2));                               \
                a3 = f2tf(__uint_as_float(a3));                               \
            }                                                                 \
            _Pragma("unroll")                                                 \
            for (int nt = 0; nt < 4; nt++)                                    \
                mma8(c[mt][nt], a0, a1, a2, a3, bf0[nt], bf1[nt]);            \
        }                                                                     \
    } }

// Pipeline: wait(kb) -> sync -> issue(kb+2) -> compute(kb). The sync
// certifies compute(kb-1) finished, so reusing slot (kb+2)%3 is safe.
#define GEMM_BODY(APTR, LDA, BPTR, LDB, NK, CVTA, MT, AI, ASTRIDE, BOFFv)     \
    extern __shared__ float smem[];                                           \
    const uint32_t smbase = (uint32_t)__cvta_generic_to_shared(smem);         \
    const int tid  = threadIdx.x;                                             \
    const int lane = tid & 31, wrp = tid >> 5;                                \
    const int l4 = lane & 3, l28 = lane >> 2;                                 \
    const int wm = (wrp >> 2) * ((MT) * 16), wn = (wrp & 3) * 32;             \
    const int lg = lane >> 3, lrow = lane & 7;                                \
    const uint32_t a_lane_off =                                               \
        (uint32_t)(((wm + (lg & 1) * 8 + lrow) * 36 + (lg >> 1) * 4) * 4);    \
    float c[MT][4][4];                                                        \
    _Pragma("unroll") for (int i = 0; i < (MT); i++)                          \
    _Pragma("unroll") for (int j = 0; j < 4; j++)                             \
    _Pragma("unroll") for (int q = 0; q < 4; q++) c[i][j][q] = 0.f;           \
    const int ar = tid >> 3, ac = (tid & 7) * 4;                              \
    const float* Abase = (APTR);                                              \
    const float* Bbase = (BPTR);                                              \
    const int LDAv = (int)(LDA), LDBv = (int)(LDB);                           \
    const int nk = (NK);                                                      \
    int st = 0;                                                               \
    GEMM_ISSUE(0, 0, AI, ASTRIDE, BOFFv); CP_COMMIT();                        \
    if (nk > 1) { GEMM_ISSUE(1, 1, AI, ASTRIDE, BOFFv); }                     \
    CP_COMMIT();                                                              \
    for (int kb = 0; kb < nk; kb++) {                                         \
        if (kb + 1 < nk) { CP_WAIT1(); } else { CP_WAIT0(); }                 \
        __syncthreads();                                                      \
        if (kb + 2 < nk) {                                                    \
            int s2 = st + 2 - ((st >= 1) ? 3 : 0);                            \
            GEMM_ISSUE(kb + 2, s2, AI, ASTRIDE, BOFFv); CP_COMMIT();          \
        }                                                                     \
        GEMM_COMPUTE(st, CVTA, MT, ASTRIDE, BOFFv);                           \
        st = (st == 2) ? 0 : st + 1;                                          \
    }

// Epilogue mapping: rows r0 = m0+wm+mt*16+l28, r1 = r0+8;
// cols n = n0+wn+nt*8+2*l4: c[mt][nt][0..1] row r0, [2..3] row r1.

// ---------------------------------------------------------------------------
__global__ void group_kernel(const int* __restrict__ cid) {
    __shared__ int s_cnt[8], s_off[8], s_cur[8];
    int t = threadIdx.x;
    if (t < 8) { s_cnt[t] = 0; s_cur[t] = 0; }
    __syncthreads();
    for (int m = t; m < BSZ; m += blockDim.x) atomicAdd(&s_cnt[cid[m]], 1);
    __syncthreads();
    if (t == 0) {
        int o = 0;
        for (int cc = 0; cc < 8; cc++) {
            s_off[cc] = o; g_off[cc] = o; g_end[cc] = o + s_cnt[cc];
            o = (o + s_cnt[cc] + 63) & ~63;   // 64-align next class
        }
        g_off[8] = o;
    }
    __syncthreads();
    for (int m = t; m < BSZ; m += blockDim.x) {
        int cc = cid[m];
        int p = s_off[cc] + atomicAdd(&s_cur[cc], 1);
        g_perm[p] = m; g_pos[m] = p;
    }
}

// ---------------------------------------------------------------------------
__global__ __launch_bounds__(256, 2)
void mlp1_kernel(const float* __restrict__ z, const int* __restrict__ cid,
                 const float* __restrict__ W1, const float* __restrict__ b1) {
    const int m0 = blockIdx.y * 128, n0 = blockIdx.x * 128;
    GEMM_BODY(z + (size_t)m0 * LATENT, LATENT, W1 + n0, HID, LATENT / 32, 1,
              4, 4, 4608, 13824);

    #pragma unroll
    for (int mt = 0; mt < 4; mt++) {
        int r0 = m0 + wm + mt * 16 + l28;
        int r1 = r0 + 8;
        const float* w0 = W1 + (size_t)(LATENT + cid[r0]) * HID;
        const float* w1 = W1 + (size_t)(LATENT + cid[r1]) * HID;
        #pragma unroll
        for (int nt = 0; nt < 4; nt++) {
            int n = n0 + wn + nt * 8 + 2 * l4;
            float2 bb = *(const float2*)&b1[n];
            float2 wa = *(const float2*)&w0[n];
            float2 wb = *(const float2*)&w1[n];
            float2 o0 = make_float2(tf32r(gelu_exact(c[mt][nt][0] + bb.x + wa.x)),
                                    tf32r(gelu_exact(c[mt][nt][1] + bb.y + wa.y)));
            float2 o1 = make_float2(tf32r(gelu_exact(c[mt][nt][2] + bb.x + wb.x)),
                                    tf32r(gelu_exact(c[mt][nt][3] + bb.y + wb.y)));
            *(float2*)&g_h[(size_t)r0 * HID + n] = o0;
            *(float2*)&g_h[(size_t)r1 * HID + n] = o1;
        }
    }
}

// ---------------------------------------------------------------------------
__global__ __launch_bounds__(256, 2)
void mlp2_kernel(const float* __restrict__ W2, const float* __restrict__ b2) {
    const int m0 = blockIdx.y * 128, n0 = blockIdx.x * 128;
    GEMM_BODY(g_h + (size_t)m0 * HID, HID, W2 + n0, HID, HID / 32, 0,
              4, 4, 4608, 13824);

    #pragma unroll
    for (int mt = 0; mt < 4; mt++) {
        int r0 = m0 + wm + mt * 16 + l28;
        int r1 = r0 + 8;
        int p0 = g_pos[r0], p1 = g_pos[r1];
        #pragma unroll
        for (int nt = 0; nt < 4; nt++) {
            int n = n0 + wn + nt * 8 + 2 * l4;
            float2 bb = *(const float2*)&b2[n];
            float2 o0 = make_float2(tf32r(gelu_exact(c[mt][nt][0] + bb.x)),
                                    tf32r(gelu_exact(c[mt][nt][1] + bb.y)));
            float2 o1 = make_float2(tf32r(gelu_exact(c[mt][nt][2] + bb.x)),
                                    tf32r(gelu_exact(c[mt][nt][3] + bb.y)));
            *(float2*)&g_Tc[(size_t)p0 * HID + n] = o0;
            *(float2*)&g_Tc[(size_t)p1 * HID + n] = o1;
        }
    }
}

// ---------------------------------------------------------------------------
// logits (M-tile 64): writes tf32-rounded exp(t@Wa + ba) + per-tile partials.
// No max-subtraction: logits are O(0.05) by construction.
// ---------------------------------------------------------------------------
__global__ __launch_bounds__(256, 3)
void logits_kernel(const float* __restrict__ Wa, const float* __restrict__ ba) {
    const int pt0 = blockIdx.y * 64;
    if (pt0 >= g_off[8]) return;
    int cls = 0;
    #pragma unroll
    for (int i = 0; i < 8; i++) if (g_off[i + 1] <= pt0) cls = i + 1;
    const int Nc = d_counts[cls];
    const int n0 = blockIdx.x * 128;
    if (n0 >= Nc) return;
    const int m0 = pt0;

    __shared__ float rowpart[4][64];

    GEMM_BODY(g_Tc + (size_t)m0 * HID, HID,
              Wa + (size_t)cls * HID * NMAX + n0, NMAX, HID / 32, 0,
              2, 2, 2304, 6912);

    const float* brow = ba + (size_t)cls * NMAX;
    #pragma unroll
    for (int mt = 0; mt < 2; mt++) {
        int lr0 = wm + mt * 16 + l28;
        int r0 = m0 + lr0;
        int r1 = r0 + 8;
        float s0 = 0.f, s1 = 0.f;
        #pragma unroll
        for (int nt = 0; nt < 4; nt++) {
            int n = n0 + wn + nt * 8 + 2 * l4;
            float2 bb = *(const float2*)&brow[n];
            float2 e0 = make_float2(tf32r(__expf(c[mt][nt][0] + bb.x)),
                                    tf32r(__expf(c[mt][nt][1] + bb.y)));
            float2 e1 = make_float2(tf32r(__expf(c[mt][nt][2] + bb.x)),
                                    tf32r(__expf(c[mt][nt][3] + bb.y)));
            s0 += e0.x + e0.y; s1 += e1.x + e1.y;
            *(float2*)&g_logits[(size_t)r0 * NMAX + n] = e0;
            *(float2*)&g_logits[(size_t)r1 * NMAX + n] = e1;
        }
        s0 += __shfl_xor_sync(0xffffffffu, s0, 1);
        s0 += __shfl_xor_sync(0xffffffffu, s0, 2);
        s1 += __shfl_xor_sync(0xffffffffu, s1, 1);
        s1 += __shfl_xor_sync(0xffffffffu, s1, 2);
        if (l4 == 0) {
            rowpart[wrp & 3][lr0] = s0;
            rowpart[wrp & 3][lr0 + 8] = s1;
        }
    }
    __syncthreads();
    if (tid < 64) {
        float s = rowpart[0][tid] + rowpart[1][tid] + rowpart[2][tid] + rowpart[3][tid];
        g_partial[(size_t)(m0 + tid) * 32 + blockIdx.x] = s;
    }
}

// ---------------------------------------------------------------------------
// out (M-tile 64): 1/sum from g_partial at entry, GEMM vs Xbuf,
// normalization + scatter in epilogue.
// ---------------------------------------------------------------------------
__global__ __launch_bounds__(256, 3)
void out_kernel(const float* __restrict__ Xbuf, float* __restrict__ out) {
    const int pt0 = blockIdx.y * 64;
    if (pt0 >= g_off[8]) return;
    int cls = 0;
    #pragma unroll
    for (int i = 0; i < 8; i++) if (g_off[i + 1] <= pt0) cls = i + 1;
    const int Nc = d_counts[cls];
    const int endc = g_end[cls];
    const int n0 = blockIdx.x * 128;
    const int m0 = pt0;

    __shared__ float s_inv[64];
    {
        int t = threadIdx.x;
        if (t < 64) {
            int ntile = Nc >> 7;
            float s = 0.f;
            for (int i = 0; i < ntile; i++)
                s += g_partial[(size_t)(pt0 + t) * 32 + i];
            s_inv[t] = 1.0f / s;    // pad rows: finite garbage, masked below
        }
    }

    GEMM_BODY(g_logits + (size_t)m0 * NMAX, NMAX,
              Xbuf + (size_t)cls * NMAX * DFEAT + n0, DFEAT, Nc / 32, 0,
              2, 2, 2304, 6912);

    #pragma unroll
    for (int mt = 0; mt < 2; mt++) {
        int r0 = m0 + wm + mt * 16 + l28;
        int r1 = r0 + 8;
        bool v0 = r0 < endc, v1 = r1 < endc;
        int dm0 = v0 ? g_perm[r0] : 0;
        int dm1 = v1 ? g_perm[r1] : 0;
        float i0 = s_inv[r0 - m0];
        float i1 = s_inv[r1 - m0];
        #pragma unroll
        for (int nt = 0; nt < 4; nt++) {
            int n = n0 + wn + nt * 8 + 2 * l4;
            if (v0) {
                float2 o0 = make_float2(c[mt][nt][0] * i0, c[mt][nt][1] * i0);
                *(float2*)&out[(size_t)dm0 * DFEAT + n] = o0;
            }
            if (v1) {
                float2 o1 = make_float2(c[mt][nt][2] * i1, c[mt][nt][3] * i1);
                *(float2*)&out[(size_t)dm1 * DFEAT + n] = o1;
            }
        }
    }
}

// ---------------------------------------------------------------------------
extern "C" void kernel_launch(void* const* d_in, const int* in_sizes, int n_in,
                              void* d_out, int out_size) {
    const float* z   = (const float*)d_in[0];
    const int*   cid = (const int*)  d_in[1];
    const float* W1  = (const float*)d_in[2];
    const float* b1  = (const float*)d_in[3];
    const float* W2  = (const float*)d_in[4];
    const float* b2  = (const float*)d_in[5];
    const float* Wa  = (const float*)d_in[6];
    const float* ba  = (const float*)d_in[7];
    const float* Xb  = (const float*)d_in[8];
    float* out = (float*)d_out;

    static int attr_done = 0;
    if (!attr_done) {
        cudaFuncSetAttribute(mlp1_kernel,   cudaFuncAttributeMaxDynamicSharedMemorySize, SMEM_BYTES_128);
        cudaFuncSetAttribute(mlp2_kernel,   cudaFuncAttributeMaxDynamicSharedMemorySize, SMEM_BYTES_128);
        cudaFuncSetAttribute(logits_kernel, cudaFuncAttributeMaxDynamicSharedMemorySize, SMEM_BYTES_64);
        cudaFuncSetAttribute(out_kernel,    cudaFuncAttributeMaxDynamicSharedMemorySize, SMEM_BYTES_64);
        attr_done = 1;
    }

    group_kernel<<<1, 1024>>>(cid);
    mlp1_kernel<<<dim3(HID / 128, BSZ / 128), 256, SMEM_BYTES_128>>>(z, cid, W1, b1);
    mlp2_kernel<<<dim3(HID / 128, BSZ / 128), 256, SMEM_BYTES_128>>>(W2, b2);
    logits_kernel<<<dim3(NMAX / 128, PADMAX / 64), 256, SMEM_BYTES_64>>>(Wa, ba);
    out_kernel<<<dim3(DFEAT / 128, PADMAX / 64), 256, SMEM_BYTES_64>>>(Xb, out);
}

// round 14
// speedup vs baseline: 1.1981x; 1.0843x over previous
#include <cuda_runtime.h>
#include <math.h>
#include <stdint.h>

// Problem constants
#define BSZ    2048
#define LATENT 128
#define NCLS   8
#define HID    1024
#define DFEAT  512
#define NMAX   4096
#define PADMAX 2560   // per-class segments 64-aligned

__constant__ int d_counts[8] = {1024,1536,2048,2560,3072,3584,3840,4096};

// Scratch (static device globals, zero-initialized)
__device__ float g_h[BSZ * HID];            // tf32-exact values
__device__ float g_Tc[PADMAX * HID];        // tf32-exact; pad rows stay 0
__device__ float g_logits[PADMAX * NMAX];   // exp(logit), tf32-exact
__device__ float g_partial[PADMAX * 32];    // per-(row, n-tile) exp sums
__device__ int   g_perm[PADMAX];
__device__ int   g_pos[BSZ];
__device__ int   g_off[9];
__device__ int   g_end[8];

__device__ __forceinline__ float gelu_exact(float v) {
    return 0.5f * v * (1.0f + erff(v * 0.70710678118654752f));
}
__device__ __forceinline__ uint32_t f2tf(float x) {
    uint32_t r; asm("cvt.rna.tf32.f32 %0, %1;" : "=r"(r) : "f"(x)); return r;
}
__device__ __forceinline__ float tf32r(float x) {
    return __uint_as_float(f2tf(x));
}
__device__ __forceinline__ void mma8(float* c, uint32_t a0, uint32_t a1,
                                     uint32_t a2, uint32_t a3,
                                     uint32_t b0, uint32_t b1) {
    asm volatile(
        "mma.sync.aligned.m16n8k8.row.col.f32.tf32.tf32.f32 "
        "{%0,%1,%2,%3}, {%4,%5,%6,%7}, {%8,%9}, {%0,%1,%2,%3};"
        : "+f"(c[0]), "+f"(c[1]), "+f"(c[2]), "+f"(c[3])
        : "r"(a0), "r"(a1), "r"(a2), "r"(a3), "r"(b0), "r"(b1));
}
// ldmatrix.x4 on tf32-as-2xb16: gives exactly the m16n8k8 tf32 A fragment.
__device__ __forceinline__ void ldsm4(uint32_t& a0, uint32_t& a1,
                                      uint32_t& a2, uint32_t& a3, uint32_t addr) {
    asm volatile("ldmatrix.sync.aligned.m8n8.x4.shared.b16 {%0,%1,%2,%3}, [%4];"
                 : "=r"(a0), "=r"(a1), "=r"(a2), "=r"(a3) : "r"(addr));
}
__device__ __forceinline__ void cp16(uint32_t dst, const float* src) {
    asm volatile("cp.async.cg.shared.global [%0], [%1], 16;" :: "r"(dst), "l"(src));
}
#define CP_COMMIT() asm volatile("cp.async.commit_group;" ::: "memory")
#define CP_WAIT1()  asm volatile("cp.async.wait_group 1;" ::: "memory")
#define CP_WAIT0()  asm volatile("cp.async.wait_group 0;" ::: "memory")

// ===========================================================================
// GEMM cores. Common: K-chunk 32, 256 threads, mma.m16n8k8 tf32, A frags via
// ldmatrix, B frags scalar LDS + rna cvt. Non-MMA instr per MMA = 4/MT + 1/NT.
//   mlp kernels:     M128xN128, warps 2x4 (MT4,NT4), 3-stage, SMEM 107520 B
//   grouped kernels: M64xN128,  warps 1x8 (MT4,NT2), 2-stage, SMEM  53248 B
// SMEM (floats): As[st][M][36] at st*ASTRIDE; Bs[st][32][136] at BOFFv+st*4352.
// ===========================================================================
#define BSF  4352
#define SMEM_MLP  ((4608 * 3 + BSF * 3) * 4)    // 107520
#define SMEM_GRP  ((2304 * 2 + BSF * 2) * 4)    //  53248

#define GEMM_PRE(APTR, LDA, BPTR, LDB, NK, MT, NT, WM_EXPR, WN_EXPR)          \
    extern __shared__ float smem[];                                           \
    const uint32_t smbase = (uint32_t)__cvta_generic_to_shared(smem);         \
    const int tid  = threadIdx.x;                                             \
    const int lane = tid & 31, wrp = tid >> 5;                                \
    const int l4 = lane & 3, l28 = lane >> 2;                                 \
    const int wm = (WM_EXPR), wn = (WN_EXPR);                                 \
    const int lg = lane >> 3, lrow = lane & 7;                                \
    const uint32_t a_lane_off =                                               \
        (uint32_t)(((wm + (lg & 1) * 8 + lrow) * 36 + (lg >> 1) * 4) * 4);    \
    float c[MT][NT][4];                                                       \
    _Pragma("unroll") for (int i = 0; i < (MT); i++)                          \
    _Pragma("unroll") for (int j = 0; j < (NT); j++)                          \
    _Pragma("unroll") for (int q = 0; q < 4; q++) c[i][j][q] = 0.f;           \
    const int ar = tid >> 3, ac = (tid & 7) * 4;                              \
    const float* Abase = (APTR);                                              \
    const float* Bbase = (BPTR);                                              \
    const int LDAv = (int)(LDA), LDBv = (int)(LDB);                           \
    const int nk = (NK);

#define GEMM_ISSUE(kb, st, AI, ASTRIDE, BOFFv)                                \
    {                                                                         \
        const float* asrc = Abase + (size_t)ar * LDAv + (kb) * 32 + ac;       \
        uint32_t adst = smbase + (uint32_t)(((st) * (ASTRIDE) + ar * 36 + ac) * 4); \
        _Pragma("unroll")                                                     \
        for (int i = 0; i < (AI); i++)                                        \
            cp16(adst + i * (32 * 36 * 4), asrc + (size_t)(i * 32) * LDAv);   \
        const float* bsrc = Bbase + (size_t)((kb) * 32 + ar) * LDBv + ac;     \
        uint32_t bdst = smbase + (uint32_t)(((BOFFv) + (st) * BSF + ar * 136 + ac) * 4); \
        _Pragma("unroll")                                                     \
        for (int i = 0; i < 4; i++)                                           \
            cp16(bdst + i * (32 * 4), bsrc + i * 32);                         \
    }

#define GEMM_COMPUTE(st, CVTA, MT, NT, ASTRIDE, BOFFv)                        \
    {                                                                         \
    const uint32_t abase = smbase + (uint32_t)(st) * ((ASTRIDE) * 4u) + a_lane_off; \
    _Pragma("unroll")                                                         \
    for (int ks = 0; ks < 4; ks++) {                                          \
        const float* Bp0 = smem + (BOFFv) + (st) * BSF + (ks * 8 + l4) * 136; \
        const float* Bp1 = Bp0 + 4 * 136;                                     \
        uint32_t bf0[NT], bf1[NT];                                            \
        _Pragma("unroll")                                                     \
        for (int nt = 0; nt < (NT); nt++) {                                   \
            int n = wn + nt * 8 + l28;                                        \
            bf0[nt] = f2tf(Bp0[n]);                                           \
            bf1[nt] = f2tf(Bp1[n]);                                           \
        }                                                                     \
        _Pragma("unroll")                                                     \
        for (int mt = 0; mt < (MT); mt++) {                                   \
            uint32_t a0, a1, a2, a3;                                          \
            ldsm4(a0, a1, a2, a3, abase + mt * 2304u + ks * 32u);             \
            if (CVTA) {                                                       \
                a0 = f2tf(__uint_as_float(a0));                               \
                a1 = f2tf(__uint_as_float(a1));                               \
                a2 = f2tf(__uint_as_float(a2));                               \
                a3 = f2tf(__uint_as_float(a3));                               \
            }                                                                 \
            _Pragma("unroll")                                                 \
            for (int nt = 0; nt < (NT); nt++)                                 \
                mma8(c[mt][nt], a0, a1, a2, a3, bf0[nt], bf1[nt]);            \
        }                                                                     \
    } }

// 3-stage pipeline: wait(kb) -> sync -> issue(kb+2) -> compute(kb).
#define GEMM_RUN3(CVTA, MT, NT, AI, ASTRIDE, BOFFv)                           \
    {                                                                         \
        int st = 0;                                                           \
        GEMM_ISSUE(0, 0, AI, ASTRIDE, BOFFv); CP_COMMIT();                    \
        if (nk > 1) { GEMM_ISSUE(1, 1, AI, ASTRIDE, BOFFv); }                 \
        CP_COMMIT();                                                          \
        for (int kb = 0; kb < nk; kb++) {                                     \
            if (kb + 1 < nk) { CP_WAIT1(); } else { CP_WAIT0(); }             \
            __syncthreads();                                                  \
            if (kb + 2 < nk) {                                                \
                int s2 = st + 2 - ((st >= 1) ? 3 : 0);                        \
                GEMM_ISSUE(kb + 2, s2, AI, ASTRIDE, BOFFv); CP_COMMIT();      \
            }                                                                 \
            GEMM_COMPUTE(st, CVTA, MT, NT, ASTRIDE, BOFFv);                   \
            st = (st == 2) ? 0 : st + 1;                                      \
        }                                                                     \
    }

// 2-stage pipeline (R7 skeleton): issue(kb+1) -> wait(kb) -> sync ->
// compute(kb) -> sync (protects buffer (kb)&1 from issue(kb+2) next iter).
#define GEMM_RUN2(CVTA, MT, NT, AI, ASTRIDE, BOFFv)                           \
    {                                                                         \
        GEMM_ISSUE(0, 0, AI, ASTRIDE, BOFFv); CP_COMMIT();                    \
        for (int kb = 0; kb < nk; kb++) {                                     \
            const int st = kb & 1;                                            \
            if (kb + 1 < nk) {                                                \
                GEMM_ISSUE(kb + 1, st ^ 1, AI, ASTRIDE, BOFFv);               \
                CP_COMMIT(); CP_WAIT1();                                      \
            } else { CP_WAIT0(); }                                            \
            __syncthreads();                                                  \
            GEMM_COMPUTE(st, CVTA, MT, NT, ASTRIDE, BOFFv);                   \
            __syncthreads();                                                  \
        }                                                                     \
    }

// Epilogue mapping: rows r0 = m0+wm+mt*16+l28, r1 = r0+8;
// cols n = n0+wn+nt*8+2*l4: c[mt][nt][0..1] row r0, [2..3] row r1.

// ---------------------------------------------------------------------------
__global__ void group_kernel(const int* __restrict__ cid) {
    __shared__ int s_cnt[8], s_off[8], s_cur[8];
    int t = threadIdx.x;
    if (t < 8) { s_cnt[t] = 0; s_cur[t] = 0; }
    __syncthreads();
    for (int m = t; m < BSZ; m += blockDim.x) atomicAdd(&s_cnt[cid[m]], 1);
    __syncthreads();
    if (t == 0) {
        int o = 0;
        for (int cc = 0; cc < 8; cc++) {
            s_off[cc] = o; g_off[cc] = o; g_end[cc] = o + s_cnt[cc];
            o = (o + s_cnt[cc] + 63) & ~63;   // 64-align next class
        }
        g_off[8] = o;
    }
    __syncthreads();
    for (int m = t; m < BSZ; m += blockDim.x) {
        int cc = cid[m];
        int p = s_off[cc] + atomicAdd(&s_cur[cc], 1);
        g_perm[p] = m; g_pos[m] = p;
    }
}

// ---------------------------------------------------------------------------
__global__ __launch_bounds__(256, 2)
void mlp1_kernel(const float* __restrict__ z, const int* __restrict__ cid,
                 const float* __restrict__ W1, const float* __restrict__ b1) {
    const int m0 = blockIdx.y * 128, n0 = blockIdx.x * 128;
    GEMM_PRE(z + (size_t)m0 * LATENT, LATENT, W1 + n0, HID, LATENT / 32,
             4, 4, (wrp >> 2) * 64, (wrp & 3) * 32);
    GEMM_RUN3(1, 4, 4, 4, 4608, 13824);

    #pragma unroll
    for (int mt = 0; mt < 4; mt++) {
        int r0 = m0 + wm + mt * 16 + l28;
        int r1 = r0 + 8;
        const float* w0 = W1 + (size_t)(LATENT + cid[r0]) * HID;
        const float* w1 = W1 + (size_t)(LATENT + cid[r1]) * HID;
        #pragma unroll
        for (int nt = 0; nt < 4; nt++) {
            int n = n0 + wn + nt * 8 + 2 * l4;
            float2 bb = *(const float2*)&b1[n];
            float2 wa = *(const float2*)&w0[n];
            float2 wb = *(const float2*)&w1[n];
            float2 o0 = make_float2(tf32r(gelu_exact(c[mt][nt][0] + bb.x + wa.x)),
                                    tf32r(gelu_exact(c[mt][nt][1] + bb.y + wa.y)));
            float2 o1 = make_float2(tf32r(gelu_exact(c[mt][nt][2] + bb.x + wb.x)),
                                    tf32r(gelu_exact(c[mt][nt][3] + bb.y + wb.y)));
            *(float2*)&g_h[(size_t)r0 * HID + n] = o0;
            *(float2*)&g_h[(size_t)r1 * HID + n] = o1;
        }
    }
}

// ---------------------------------------------------------------------------
__global__ __launch_bounds__(256, 2)
void mlp2_kernel(const float* __restrict__ W2, const float* __restrict__ b2) {
    const int m0 = blockIdx.y * 128, n0 = blockIdx.x * 128;
    GEMM_PRE(g_h + (size_t)m0 * HID, HID, W2 + n0, HID, HID / 32,
             4, 4, (wrp >> 2) * 64, (wrp & 3) * 32);
    GEMM_RUN3(0, 4, 4, 4, 4608, 13824);

    #pragma unroll
    for (int mt = 0; mt < 4; mt++) {
        int r0 = m0 + wm + mt * 16 + l28;
        int r1 = r0 + 8;
        int p0 = g_pos[r0], p1 = g_pos[r1];
        #pragma unroll
        for (int nt = 0; nt < 4; nt++) {
            int n = n0 + wn + nt * 8 + 2 * l4;
            float2 bb = *(const float2*)&b2[n];
            float2 o0 = make_float2(tf32r(gelu_exact(c[mt][nt][0] + bb.x)),
                                    tf32r(gelu_exact(c[mt][nt][1] + bb.y)));
            float2 o1 = make_float2(tf32r(gelu_exact(c[mt][nt][2] + bb.x)),
                                    tf32r(gelu_exact(c[mt][nt][3] + bb.y)));
            *(float2*)&g_Tc[(size_t)p0 * HID + n] = o0;
            *(float2*)&g_Tc[(size_t)p1 * HID + n] = o1;
        }
    }
}

// ---------------------------------------------------------------------------
// logits (M64xN128, warps 1x8): writes tf32-rounded exp(t@Wa + ba) +
// per-(row, n-tile) partials. No max-subtraction: logits are O(0.05).
// ---------------------------------------------------------------------------
__global__ __launch_bounds__(256, 3)
void logits_kernel(const float* __restrict__ Wa, const float* __restrict__ ba) {
    const int pt0 = blockIdx.y * 64;
    if (pt0 >= g_off[8]) return;
    int cls = 0;
    #pragma unroll
    for (int i = 0; i < 8; i++) if (g_off[i + 1] <= pt0) cls = i + 1;
    const int Nc = d_counts[cls];
    const int n0 = blockIdx.x * 128;
    if (n0 >= Nc) return;
    const int m0 = pt0;

    __shared__ float rowpart[8][64];

    GEMM_PRE(g_Tc + (size_t)m0 * HID, HID,
             Wa + (size_t)cls * HID * NMAX + n0, NMAX, HID / 32,
             4, 2, 0, wrp * 16);
    GEMM_RUN2(0, 4, 2, 2, 2304, 4608);

    const float* brow = ba + (size_t)cls * NMAX;
    #pragma unroll
    for (int mt = 0; mt < 4; mt++) {
        int lr0 = mt * 16 + l28;
        int r0 = m0 + lr0;
        int r1 = r0 + 8;
        float s0 = 0.f, s1 = 0.f;
        #pragma unroll
        for (int nt = 0; nt < 2; nt++) {
            int n = n0 + wn + nt * 8 + 2 * l4;
            float2 bb = *(const float2*)&brow[n];
            float2 e0 = make_float2(tf32r(__expf(c[mt][nt][0] + bb.x)),
                                    tf32r(__expf(c[mt][nt][1] + bb.y)));
            float2 e1 = make_float2(tf32r(__expf(c[mt][nt][2] + bb.x)),
                                    tf32r(__expf(c[mt][nt][3] + bb.y)));
            s0 += e0.x + e0.y; s1 += e1.x + e1.y;
            *(float2*)&g_logits[(size_t)r0 * NMAX + n] = e0;
            *(float2*)&g_logits[(size_t)r1 * NMAX + n] = e1;
        }
        // reduce across the 4 l4-lanes sharing these rows (warp covers 16 cols)
        s0 += __shfl_xor_sync(0xffffffffu, s0, 1);
        s0 += __shfl_xor_sync(0xffffffffu, s0, 2);
        s1 += __shfl_xor_sync(0xffffffffu, s1, 1);
        s1 += __shfl_xor_sync(0xffffffffu, s1, 2);
        if (l4 == 0) {
            rowpart[wrp][lr0] = s0;
            rowpart[wrp][lr0 + 8] = s1;
        }
    }
    __syncthreads();
    if (tid < 64) {
        float s = 0.f;
        #pragma unroll
        for (int w = 0; w < 8; w++) s += rowpart[w][tid];
        g_partial[(size_t)(m0 + tid) * 32 + blockIdx.x] = s;
    }
}

// ---------------------------------------------------------------------------
// out (M64xN128, warps 1x8): 1/sum from g_partial at entry, GEMM vs Xbuf,
// normalization + scatter in epilogue.
// ---------------------------------------------------------------------------
__global__ __launch_bounds__(256, 3)
void out_kernel(const float* __restrict__ Xbuf, float* __restrict__ out) {
    const int pt0 = blockIdx.y * 64;
    if (pt0 >= g_off[8]) return;
    int cls = 0;
    #pragma unroll
    for (int i = 0; i < 8; i++) if (g_off[i + 1] <= pt0) cls = i + 1;
    const int Nc = d_counts[cls];
    const int endc = g_end[cls];
    const int n0 = blockIdx.x * 128;
    const int m0 = pt0;

    __shared__ float s_inv[64];
    if (threadIdx.x < 64) {
        int ntile = Nc >> 7;
        float s = 0.f;
        for (int i = 0; i < ntile; i++)
            s += g_partial[(size_t)(pt0 + threadIdx.x) * 32 + i];
        s_inv[threadIdx.x] = 1.0f / s;    // pad rows: finite garbage, masked below
    }

    GEMM_PRE(g_logits + (size_t)m0 * NMAX, NMAX,
             Xbuf + (size_t)cls * NMAX * DFEAT + n0, DFEAT, Nc / 32,
             4, 2, 0, wrp * 16);
    GEMM_RUN2(0, 4, 2, 2, 2304, 4608);

    #pragma unroll
    for (int mt = 0; mt < 4; mt++) {
        int r0 = m0 + mt * 16 + l28;
        int r1 = r0 + 8;
        bool v0 = r0 < endc, v1 = r1 < endc;
        int dm0 = v0 ? g_perm[r0] : 0;
        int dm1 = v1 ? g_perm[r1] : 0;
        float i0 = s_inv[r0 - m0];
        float i1 = s_inv[r1 - m0];
        #pragma unroll
        for (int nt = 0; nt < 2; nt++) {
            int n = n0 + wn + nt * 8 + 2 * l4;
            if (v0) {
                float2 o0 = make_float2(c[mt][nt][0] * i0, c[mt][nt][1] * i0);
                *(float2*)&out[(size_t)dm0 * DFEAT + n] = o0;
            }
            if (v1) {
                float2 o1 = make_float2(c[mt][nt][2] * i1, c[mt][nt][3] * i1);
                *(float2*)&out[(size_t)dm1 * DFEAT + n] = o1;
            }
        }
    }
}

// ---------------------------------------------------------------------------
extern "C" void kernel_launch(void* const* d_in, const int* in_sizes, int n_in,
                              void* d_out, int out_size) {
    const float* z   = (const float*)d_in[0];
    const int*   cid = (const int*)  d_in[1];
    const float* W1  = (const float*)d_in[2];
    const float* b1  = (const float*)d_in[3];
    const float* W2  = (const float*)d_in[4];
    const float* b2  = (const float*)d_in[5];
    const float* Wa  = (const float*)d_in[6];
    const float* ba  = (const float*)d_in[7];
    const float* Xb  = (const float*)d_in[8];
    float* out = (float*)d_out;

    static int attr_done = 0;
    if (!attr_done) {
        cudaFuncSetAttribute(mlp1_kernel,   cudaFuncAttributeMaxDynamicSharedMemorySize, SMEM_MLP);
        cudaFuncSetAttribute(mlp2_kernel,   cudaFuncAttributeMaxDynamicSharedMemorySize, SMEM_MLP);
        cudaFuncSetAttribute(logits_kernel, cudaFuncAttributeMaxDynamicSharedMemorySize, SMEM_GRP);
        cudaFuncSetAttribute(out_kernel,    cudaFuncAttributeMaxDynamicSharedMemorySize, SMEM_GRP);
        attr_done = 1;
    }

    group_kernel<<<1, 1024>>>(cid);
    mlp1_kernel<<<dim3(HID / 128, BSZ / 128), 256, SMEM_MLP>>>(z, cid, W1, b1);
    mlp2_kernel<<<dim3(HID / 128, BSZ / 128), 256, SMEM_MLP>>>(W2, b2);
    logits_kernel<<<dim3(NMAX / 128, PADMAX / 64), 256, SMEM_GRP>>>(Wa, ba);
    out_kernel<<<dim3(DFEAT / 128, PADMAX / 64), 256, SMEM_GRP>>>(Xb, out);
}

// round 15
// speedup vs baseline: 1.2204x; 1.0187x over previous
#include <cuda_runtime.h>
#include <math.h>
#include <stdint.h>

// Problem constants
#define BSZ    2048
#define LATENT 128
#define NCLS   8
#define HID    1024
#define DFEAT  512
#define NMAX   4096
#define PADMAX 2560   // per-class segments 64-aligned

__constant__ int d_counts[8] = {1024,1536,2048,2560,3072,3584,3840,4096};

// Scratch (static device globals, zero-initialized)
__device__ float g_h[BSZ * HID];            // tf32-exact values
__device__ float g_Tc[PADMAX * HID];        // tf32-exact; pad rows stay 0
__device__ float g_logits[PADMAX * NMAX];   // exp(logit), tf32-exact
__device__ float g_partial[PADMAX * 32];    // per-(row, n-tile) exp sums
__device__ int   g_perm[PADMAX];
__device__ int   g_pos[BSZ];
__device__ int   g_off[9];
__device__ int   g_end[8];

__device__ __forceinline__ float gelu_exact(float v) {
    return 0.5f * v * (1.0f + erff(v * 0.70710678118654752f));
}
__device__ __forceinline__ uint32_t f2tf(float x) {
    uint32_t r; asm("cvt.rna.tf32.f32 %0, %1;" : "=r"(r) : "f"(x)); return r;
}
__device__ __forceinline__ float tf32r(float x) {
    return __uint_as_float(f2tf(x));
}
__device__ __forceinline__ void mma8(float* c, uint32_t a0, uint32_t a1,
                                     uint32_t a2, uint32_t a3,
                                     uint32_t b0, uint32_t b1) {
    asm volatile(
        "mma.sync.aligned.m16n8k8.row.col.f32.tf32.tf32.f32 "
        "{%0,%1,%2,%3}, {%4,%5,%6,%7}, {%8,%9}, {%0,%1,%2,%3};"
        : "+f"(c[0]), "+f"(c[1]), "+f"(c[2]), "+f"(c[3])
        : "r"(a0), "r"(a1), "r"(a2), "r"(a3), "r"(b0), "r"(b1));
}
// ldmatrix.x4 on tf32-as-2xb16: gives exactly the m16n8k8 tf32 A fragment.
__device__ __forceinline__ void ldsm4(uint32_t& a0, uint32_t& a1,
                                      uint32_t& a2, uint32_t& a3, uint32_t addr) {
    asm volatile("ldmatrix.sync.aligned.m8n8.x4.shared.b16 {%0,%1,%2,%3}, [%4];"
                 : "=r"(a0), "=r"(a1), "=r"(a2), "=r"(a3) : "r"(addr));
}
__device__ __forceinline__ void cp16(uint32_t dst, const float* src) {
    asm volatile("cp.async.cg.shared.global [%0], [%1], 16;" :: "r"(dst), "l"(src));
}
#define CP_COMMIT() asm volatile("cp.async.commit_group;" ::: "memory")
#define CP_WAIT1()  asm volatile("cp.async.wait_group 1;" ::: "memory")
#define CP_WAIT0()  asm volatile("cp.async.wait_group 0;" ::: "memory")

// ===========================================================================
// GEMM cores. Common: K-chunk 32, 256 threads, mma.m16n8k8 tf32, A frags via
// ldmatrix, B frags scalar LDS + rna cvt.
//   mlp:    M128xN128, warps 2x4 (MT4,NT4), 3-stage            SMEM 107520 B
//   logits: M64xN256,  warps 1x8 (MT4,NT4), 2-stage            SMEM  86016 B
//   out:    M64xN128,  warps 1x8 (MT4,NT2), 2-stage            SMEM  53248 B
// SMEM (floats): As[st][M][36] at st*ASTRIDE; Bs[st][32][BNP] at BOFF+st*BSF.
// ===========================================================================
#define SMEM_MLP  ((4608 * 3 + 4352 * 3) * 4)   // 107520
#define SMEM_LOG  ((2304 * 2 + 8448 * 2) * 4)   //  86016
#define SMEM_OUT  ((2304 * 2 + 4352 * 2) * 4)   //  53248

#define GEMM_PRE(APTR, LDA, BPTR, LDB, NK, MT, NT, WM_EXPR, WN_EXPR)          \
    extern __shared__ float smem[];                                           \
    const uint32_t smbase = (uint32_t)__cvta_generic_to_shared(smem);         \
    const int tid  = threadIdx.x;                                             \
    const int lane = tid & 31, wrp = tid >> 5;                                \
    const int l4 = lane & 3, l28 = lane >> 2;                                 \
    const int wm = (WM_EXPR), wn = (WN_EXPR);                                 \
    const int lg = lane >> 3, lrow = lane & 7;                                \
    const uint32_t a_lane_off =                                               \
        (uint32_t)(((wm + (lg & 1) * 8 + lrow) * 36 + (lg >> 1) * 4) * 4);    \
    float c[MT][NT][4];                                                       \
    _Pragma("unroll") for (int i = 0; i < (MT); i++)                          \
    _Pragma("unroll") for (int j = 0; j < (NT); j++)                          \
    _Pragma("unroll") for (int q = 0; q < 4; q++) c[i][j][q] = 0.f;           \
    const int ar = tid >> 3, ac = (tid & 7) * 4;                              \
    const float* Abase = (APTR);                                              \
    const float* Bbase = (BPTR);                                              \
    const int LDAv = (int)(LDA), LDBv = (int)(LDB);                           \
    const int nk = (NK);

#define GEMM_ISSUE(kb, st, AI, ASTRIDE, BOFFv, BSFv, BNP, BI)                 \
    {                                                                         \
        const float* asrc = Abase + (size_t)ar * LDAv + (kb) * 32 + ac;       \
        uint32_t adst = smbase + (uint32_t)(((st) * (ASTRIDE) + ar * 36 + ac) * 4); \
        _Pragma("unroll")                                                     \
        for (int i = 0; i < (AI); i++)                                        \
            cp16(adst + i * (32 * 36 * 4), asrc + (size_t)(i * 32) * LDAv);   \
        const float* bsrc = Bbase + (size_t)((kb) * 32 + ar) * LDBv + ac;     \
        uint32_t bdst = smbase + (uint32_t)(((BOFFv) + (st) * (BSFv) + ar * (BNP) + ac) * 4); \
        _Pragma("unroll")                                                     \
        for (int i = 0; i < (BI); i++)                                        \
            cp16(bdst + i * (32 * 4), bsrc + i * 32);                         \
    }

#define GEMM_COMPUTE(st, CVTA, MT, NT, ASTRIDE, BOFFv, BSFv, BNP)             \
    {                                                                         \
    const uint32_t abase = smbase + (uint32_t)(st) * ((ASTRIDE) * 4u) + a_lane_off; \
    _Pragma("unroll")                                                         \
    for (int ks = 0; ks < 4; ks++) {                                          \
        const float* Bp0 = smem + (BOFFv) + (st) * (BSFv) + (ks * 8 + l4) * (BNP); \
        const float* Bp1 = Bp0 + 4 * (BNP);                                   \
        uint32_t bf0[NT], bf1[NT];                                            \
        _Pragma("unroll")                                                     \
        for (int nt = 0; nt < (NT); nt++) {                                   \
            int n = wn + nt * 8 + l28;                                        \
            bf0[nt] = f2tf(Bp0[n]);                                           \
            bf1[nt] = f2tf(Bp1[n]);                                           \
        }                                                                     \
        _Pragma("unroll")                                                     \
        for (int mt = 0; mt < (MT); mt++) {                                   \
            uint32_t a0, a1, a2, a3;                                          \
            ldsm4(a0, a1, a2, a3, abase + mt * 2304u + ks * 32u);             \
            if (CVTA) {                                                       \
                a0 = f2tf(__uint_as_float(a0));                               \
                a1 = f2tf(__uint_as_float(a1));                               \
                a2 = f2tf(__uint_as_float(a2));                               \
                a3 = f2tf(__uint_as_float(a3));                               \
            }                                                                 \
            _Pragma("unroll")                                                 \
            for (int nt = 0; nt < (NT); nt++)                                 \
                mma8(c[mt][nt], a0, a1, a2, a3, bf0[nt], bf1[nt]);            \
        }                                                                     \
    } }

// 3-stage pipeline: wait(kb) -> sync -> issue(kb+2) -> compute(kb).
#define GEMM_RUN3(CVTA, MT, NT, AI, ASTRIDE, BOFFv, BSFv, BNP, BI)            \
    {                                                                         \
        int st = 0;                                                           \
        GEMM_ISSUE(0, 0, AI, ASTRIDE, BOFFv, BSFv, BNP, BI); CP_COMMIT();     \
        if (nk > 1) { GEMM_ISSUE(1, 1, AI, ASTRIDE, BOFFv, BSFv, BNP, BI); }  \
        CP_COMMIT();                                                          \
        for (int kb = 0; kb < nk; kb++) {                                     \
            if (kb + 1 < nk) { CP_WAIT1(); } else { CP_WAIT0(); }             \
            __syncthreads();                                                  \
            if (kb + 2 < nk) {                                                \
                int s2 = st + 2 - ((st >= 1) ? 3 : 0);                        \
                GEMM_ISSUE(kb + 2, s2, AI, ASTRIDE, BOFFv, BSFv, BNP, BI);    \
                CP_COMMIT();                                                  \
            }                                                                 \
            GEMM_COMPUTE(st, CVTA, MT, NT, ASTRIDE, BOFFv, BSFv, BNP);        \
            st = (st == 2) ? 0 : st + 1;                                      \
        }                                                                     \
    }

// 2-stage pipeline: issue(kb+1) -> wait(kb) -> sync -> compute(kb) -> sync.
#define GEMM_RUN2(CVTA, MT, NT, AI, ASTRIDE, BOFFv, BSFv, BNP, BI)            \
    {                                                                         \
        GEMM_ISSUE(0, 0, AI, ASTRIDE, BOFFv, BSFv, BNP, BI); CP_COMMIT();     \
        for (int kb = 0; kb < nk; kb++) {                                     \
            const int st = kb & 1;                                            \
            if (kb + 1 < nk) {                                                \
                GEMM_ISSUE(kb + 1, st ^ 1, AI, ASTRIDE, BOFFv, BSFv, BNP, BI); \
                CP_COMMIT(); CP_WAIT1();                                      \
            } else { CP_WAIT0(); }                                            \
            __syncthreads();                                                  \
            GEMM_COMPUTE(st, CVTA, MT, NT, ASTRIDE, BOFFv, BSFv, BNP);        \
            __syncthreads();                                                  \
        }                                                                     \
    }

// Epilogue mapping: rows r0 = m0+wm+mt*16+l28, r1 = r0+8;
// cols n = n0+wn+nt*8+2*l4: c[mt][nt][0..1] row r0, [2..3] row r1.

// ---------------------------------------------------------------------------
__global__ void group_kernel(const int* __restrict__ cid) {
    __shared__ int s_cnt[8], s_off[8], s_cur[8];
    int t = threadIdx.x;
    if (t < 8) { s_cnt[t] = 0; s_cur[t] = 0; }
    __syncthreads();
    for (int m = t; m < BSZ; m += blockDim.x) atomicAdd(&s_cnt[cid[m]], 1);
    __syncthreads();
    if (t == 0) {
        int o = 0;
        for (int cc = 0; cc < 8; cc++) {
            s_off[cc] = o; g_off[cc] = o; g_end[cc] = o + s_cnt[cc];
            o = (o + s_cnt[cc] + 63) & ~63;   // 64-align next class
        }
        g_off[8] = o;
    }
    __syncthreads();
    for (int m = t; m < BSZ; m += blockDim.x) {
        int cc = cid[m];
        int p = s_off[cc] + atomicAdd(&s_cur[cc], 1);
        g_perm[p] = m; g_pos[m] = p;
    }
}

// ---------------------------------------------------------------------------
__global__ __launch_bounds__(256, 2)
void mlp1_kernel(const float* __restrict__ z, const int* __restrict__ cid,
                 const float* __restrict__ W1, const float* __restrict__ b1) {
    const int m0 = blockIdx.y * 128, n0 = blockIdx.x * 128;
    GEMM_PRE(z + (size_t)m0 * LATENT, LATENT, W1 + n0, HID, LATENT / 32,
             4, 4, (wrp >> 2) * 64, (wrp & 3) * 32);
    GEMM_RUN3(1, 4, 4, 4, 4608, 13824, 4352, 136, 4);

    #pragma unroll
    for (int mt = 0; mt < 4; mt++) {
        int r0 = m0 + wm + mt * 16 + l28;
        int r1 = r0 + 8;
        const float* w0 = W1 + (size_t)(LATENT + cid[r0]) * HID;
        const float* w1 = W1 + (size_t)(LATENT + cid[r1]) * HID;
        #pragma unroll
        for (int nt = 0; nt < 4; nt++) {
            int n = n0 + wn + nt * 8 + 2 * l4;
            float2 bb = *(const float2*)&b1[n];
            float2 wa = *(const float2*)&w0[n];
            float2 wb = *(const float2*)&w1[n];
            float2 o0 = make_float2(tf32r(gelu_exact(c[mt][nt][0] + bb.x + wa.x)),
                                    tf32r(gelu_exact(c[mt][nt][1] + bb.y + wa.y)));
            float2 o1 = make_float2(tf32r(gelu_exact(c[mt][nt][2] + bb.x + wb.x)),
                                    tf32r(gelu_exact(c[mt][nt][3] + bb.y + wb.y)));
            *(float2*)&g_h[(size_t)r0 * HID + n] = o0;
            *(float2*)&g_h[(size_t)r1 * HID + n] = o1;
        }
    }
}

// ---------------------------------------------------------------------------
__global__ __launch_bounds__(256, 2)
void mlp2_kernel(const float* __restrict__ W2, const float* __restrict__ b2) {
    const int m0 = blockIdx.y * 128, n0 = blockIdx.x * 128;
    GEMM_PRE(g_h + (size_t)m0 * HID, HID, W2 + n0, HID, HID / 32,
             4, 4, (wrp >> 2) * 64, (wrp & 3) * 32);
    GEMM_RUN3(0, 4, 4, 4, 4608, 13824, 4352, 136, 4);

    #pragma unroll
    for (int mt = 0; mt < 4; mt++) {
        int r0 = m0 + wm + mt * 16 + l28;
        int r1 = r0 + 8;
        int p0 = g_pos[r0], p1 = g_pos[r1];
        #pragma unroll
        for (int nt = 0; nt < 4; nt++) {
            int n = n0 + wn + nt * 8 + 2 * l4;
            float2 bb = *(const float2*)&b2[n];
            float2 o0 = make_float2(tf32r(gelu_exact(c[mt][nt][0] + bb.x)),
                                    tf32r(gelu_exact(c[mt][nt][1] + bb.y)));
            float2 o1 = make_float2(tf32r(gelu_exact(c[mt][nt][2] + bb.x)),
                                    tf32r(gelu_exact(c[mt][nt][3] + bb.y)));
            *(float2*)&g_Tc[(size_t)p0 * HID + n] = o0;
            *(float2*)&g_Tc[(size_t)p1 * HID + n] = o1;
        }
    }
}

// ---------------------------------------------------------------------------
// logits (M64xN256, warps 1x8, MT4 NT4): exp(t@Wa + ba) + per-tile partials.
// All class counts divide 256, so N-tiles are never ragged.
// ---------------------------------------------------------------------------
__global__ __launch_bounds__(256, 2)
void logits_kernel(const float* __restrict__ Wa, const float* __restrict__ ba) {
    const int pt0 = blockIdx.y * 64;
    if (pt0 >= g_off[8]) return;
    int cls = 0;
    #pragma unroll
    for (int i = 0; i < 8; i++) if (g_off[i + 1] <= pt0) cls = i + 1;
    const int Nc = d_counts[cls];
    const int n0 = blockIdx.x * 256;
    if (n0 >= Nc) return;
    const int m0 = pt0;

    __shared__ float rowpart[8][64];

    GEMM_PRE(g_Tc + (size_t)m0 * HID, HID,
             Wa + (size_t)cls * HID * NMAX + n0, NMAX, HID / 32,
             4, 4, 0, wrp * 32);
    GEMM_RUN2(0, 4, 4, 2, 2304, 4608, 8448, 264, 8);

    const float* brow = ba + (size_t)cls * NMAX;
    #pragma unroll
    for (int mt = 0; mt < 4; mt++) {
        int lr0 = mt * 16 + l28;
        int r0 = m0 + lr0;
        int r1 = r0 + 8;
        float s0 = 0.f, s1 = 0.f;
        #pragma unroll
        for (int nt = 0; nt < 4; nt++) {
            int n = n0 + wn + nt * 8 + 2 * l4;
            float2 bb = *(const float2*)&brow[n];
            float2 e0 = make_float2(tf32r(__expf(c[mt][nt][0] + bb.x)),
                                    tf32r(__expf(c[mt][nt][1] + bb.y)));
            float2 e1 = make_float2(tf32r(__expf(c[mt][nt][2] + bb.x)),
                                    tf32r(__expf(c[mt][nt][3] + bb.y)));
            s0 += e0.x + e0.y; s1 += e1.x + e1.y;
            *(float2*)&g_logits[(size_t)r0 * NMAX + n] = e0;
            *(float2*)&g_logits[(size_t)r1 * NMAX + n] = e1;
        }
        s0 += __shfl_xor_sync(0xffffffffu, s0, 1);
        s0 += __shfl_xor_sync(0xffffffffu, s0, 2);
        s1 += __shfl_xor_sync(0xffffffffu, s1, 1);
        s1 += __shfl_xor_sync(0xffffffffu, s1, 2);
        if (l4 == 0) {
            rowpart[wrp][lr0] = s0;
            rowpart[wrp][lr0 + 8] = s1;
        }
    }
    __syncthreads();
    if (tid < 64) {
        float s = 0.f;
        #pragma unroll
        for (int w = 0; w < 8; w++) s += rowpart[w][tid];
        g_partial[(size_t)(m0 + tid) * 32 + blockIdx.x] = s;   // blockIdx.x < 16
    }
}

// ---------------------------------------------------------------------------
// out (M64xN128, warps 1x8, MT4 NT2): 1/sum from g_partial (256-col tiles),
// GEMM vs Xbuf, normalization + scatter in epilogue.
// ---------------------------------------------------------------------------
__global__ __launch_bounds__(256, 3)
void out_kernel(const float* __restrict__ Xbuf, float* __restrict__ out) {
    const int pt0 = blockIdx.y * 64;
    if (pt0 >= g_off[8]) return;
    int cls = 0;
    #pragma unroll
    for (int i = 0; i < 8; i++) if (g_off[i + 1] <= pt0) cls = i + 1;
    const int Nc = d_counts[cls];
    const int endc = g_end[cls];
    const int n0 = blockIdx.x * 128;
    const int m0 = pt0;

    __shared__ float s_inv[64];
    if (threadIdx.x < 64) {
        int ntile = Nc >> 8;                 // 256-col logits tiles
        float s = 0.f;
        for (int i = 0; i < ntile; i++)
            s += g_partial[(size_t)(pt0 + threadIdx.x) * 32 + i];
        s_inv[threadIdx.x] = 1.0f / s;       // pad rows: finite garbage, masked
    }

    GEMM_PRE(g_logits + (size_t)m0 * NMAX, NMAX,
             Xbuf + (size_t)cls * NMAX * DFEAT + n0, DFEAT, Nc / 32,
             4, 2, 0, wrp * 16);
    GEMM_RUN2(0, 4, 2, 2, 2304, 4608, 4352, 136, 4);

    #pragma unroll
    for (int mt = 0; mt < 4; mt++) {
        int r0 = m0 + mt * 16 + l28;
        int r1 = r0 + 8;
        bool v0 = r0 < endc, v1 = r1 < endc;
        int dm0 = v0 ? g_perm[r0] : 0;
        int dm1 = v1 ? g_perm[r1] : 0;
        float i0 = s_inv[r0 - m0];
        float i1 = s_inv[r1 - m0];
        #pragma unroll
        for (int nt = 0; nt < 2; nt++) {
            int n = n0 + wn + nt * 8 + 2 * l4;
            if (v0) {
                float2 o0 = make_float2(c[mt][nt][0] * i0, c[mt][nt][1] * i0);
                *(float2*)&out[(size_t)dm0 * DFEAT + n] = o0;
            }
            if (v1) {
                float2 o1 = make_float2(c[mt][nt][2] * i1, c[mt][nt][3] * i1);
                *(float2*)&out[(size_t)dm1 * DFEAT + n] = o1;
            }
        }
    }
}

// ---------------------------------------------------------------------------
extern "C" void kernel_launch(void* const* d_in, const int* in_sizes, int n_in,
                              void* d_out, int out_size) {
    const float* z   = (const float*)d_in[0];
    const int*   cid = (const int*)  d_in[1];
    const float* W1  = (const float*)d_in[2];
    const float* b1  = (const float*)d_in[3];
    const float* W2  = (const float*)d_in[4];
    const float* b2  = (const float*)d_in[5];
    const float* Wa  = (const float*)d_in[6];
    const float* ba  = (const float*)d_in[7];
    const float* Xb  = (const float*)d_in[8];
    float* out = (float*)d_out;

    static int attr_done = 0;
    if (!attr_done) {
        cudaFuncSetAttribute(mlp1_kernel,   cudaFuncAttributeMaxDynamicSharedMemorySize, SMEM_MLP);
        cudaFuncSetAttribute(mlp2_kernel,   cudaFuncAttributeMaxDynamicSharedMemorySize, SMEM_MLP);
        cudaFuncSetAttribute(logits_kernel, cudaFuncAttributeMaxDynamicSharedMemorySize, SMEM_LOG);
        cudaFuncSetAttribute(out_kernel,    cudaFuncAttributeMaxDynamicSharedMemorySize, SMEM_OUT);
        attr_done = 1;
    }

    group_kernel<<<1, 1024>>>(cid);
    mlp1_kernel<<<dim3(HID / 128, BSZ / 128), 256, SMEM_MLP>>>(z, cid, W1, b1);
    mlp2_kernel<<<dim3(HID / 128, BSZ / 128), 256, SMEM_MLP>>>(W2, b2);
    logits_kernel<<<dim3(NMAX / 256, PADMAX / 64), 256, SMEM_LOG>>>(Wa, ba);
    out_kernel<<<dim3(DFEAT / 128, PADMAX / 64), 256, SMEM_OUT>>>(Xb, out);
}